// round 3
// baseline (speedup 1.0000x reference)
#include <cuda_runtime.h>
#include <cstdint>

// PQLayer forward on GB300 (sm_103a) — v3: 2 b's per thread to halve the
// broadcast-LDS stream (L1 was the top pipe at 70.8% in v2).
//
// codes = stop_gradient(hard - soft) + soft == hard (one-hot) numerically.
//   k*[b,m] = argmax_k <x[b, m*8:(m+1)*8], C[m,k,:]>
//   codes   = streamed zeros + scattered 1.0
//   x_hat   = C[m, k*, :]

#define BB 16384
#define MM 64
#define KK 256
#define DD 8
#define FEAT (MM * DD)          // 512
#define CHUNK_B 512             // b per block: 8 warps x 64 b

using u64 = unsigned long long;

__device__ __forceinline__ u64 pack2(float lo, float hi) {
    u64 r;
    uint32_t a = __float_as_uint(lo), b = __float_as_uint(hi);
    asm("mov.b64 %0, {%1, %2};" : "=l"(r) : "r"(a), "r"(b));
    return r;
}

__device__ __forceinline__ void unpack2(u64 v, float& lo, float& hi) {
    uint32_t a, b;
    asm("mov.b64 {%0, %1}, %2;" : "=r"(a), "=r"(b) : "l"(v));
    lo = __uint_as_float(a);
    hi = __uint_as_float(b);
}

// Packed dual fp32 FMA (Blackwell FFMA2): IEEE fp32 per lane.
__device__ __forceinline__ u64 fma2(u64 a, u64 b, u64 c) {
    u64 r;
    asm("fma.rn.f32x2 %0, %1, %2, %3;" : "=l"(r) : "l"(a), "l"(b), "l"(c));
    return r;
}

__global__ void __launch_bounds__(256)
pq_forward_v3(const float* __restrict__ x, const float* __restrict__ C,
              float* __restrict__ xhat, float* __restrict__ codes)
{
    const int m    = blockIdx.x;
    const int tid  = threadIdx.x;
    const int lane = tid & 31;
    const int w    = tid >> 5;

    // cpk[j*8 + d] = { C[m][2j][d], C[m][2j+1][d] }  (k-pair packed, 8 KB)
    __shared__ __align__(16) u64    cpk[128 * 8];
    __shared__ __align__(16) float4 craw[KK * 2];     // raw copy for x_hat gather

    // ---- stage C[m] (8 KB, coalesced) into both smem views ----
    {
        const float4* C4 = reinterpret_cast<const float4*>(C) + (size_t)m * (KK * 2);
#pragma unroll
        for (int q = tid; q < KK * 2; q += 256) {
            float4 f = C4[q];
            craw[q] = f;
            const int k = q >> 1, h = (q & 1) * 4;
            const int j = k >> 1, half = k & 1;
            float vals[4] = {f.x, f.y, f.z, f.w};
#pragma unroll
            for (int dd = 0; dd < 4; dd++)
                reinterpret_cast<uint32_t*>(&cpk[j * 8 + h + dd])[half] =
                    __float_as_uint(vals[dd]);
        }
    }
    __syncthreads();

    const int b0w = blockIdx.y * CHUNK_B + w * 64;   // warp's first b (owns 64)
    const int ba  = b0w + lane;                      // this thread's b #0
    const int bb  = b0w + 32 + lane;                 // this thread's b #1

    // ---- load x for both b's and duplicate-pack for f32x2 ----
    const float4* x4 = reinterpret_cast<const float4*>(x);
    const float4 a0 = x4[(size_t)ba * (FEAT / 4) + m * 2];
    const float4 a1 = x4[(size_t)ba * (FEAT / 4) + m * 2 + 1];
    const float4 b0 = x4[(size_t)bb * (FEAT / 4) + m * 2];
    const float4 b1 = x4[(size_t)bb * (FEAT / 4) + m * 2 + 1];

    u64 xpa[8], xpb[8];
    xpa[0] = pack2(a0.x, a0.x); xpa[1] = pack2(a0.y, a0.y);
    xpa[2] = pack2(a0.z, a0.z); xpa[3] = pack2(a0.w, a0.w);
    xpa[4] = pack2(a1.x, a1.x); xpa[5] = pack2(a1.y, a1.y);
    xpa[6] = pack2(a1.z, a1.z); xpa[7] = pack2(a1.w, a1.w);
    xpb[0] = pack2(b0.x, b0.x); xpb[1] = pack2(b0.y, b0.y);
    xpb[2] = pack2(b0.z, b0.z); xpb[3] = pack2(b0.w, b0.w);
    xpb[4] = pack2(b1.x, b1.x); xpb[5] = pack2(b1.y, b1.y);
    xpb[6] = pack2(b1.z, b1.z); xpb[7] = pack2(b1.w, b1.w);

    // ---- stream zeros for this warp's 64 code rows (coalesced STG.128) ----
    // Issued before the k-loop so DRAM is busy while we compute.
    {
        const float4 z = make_float4(0.f, 0.f, 0.f, 0.f);
        float4* crow = reinterpret_cast<float4*>(codes) +
                       ((size_t)b0w * MM + m) * (KK / 4) + lane;
#pragma unroll 8
        for (int r = 0; r < 64; r++) {
            __stcs(crow, z);            // k[4*lane .. 4*lane+4)
            __stcs(crow + 32, z);       // k[128+4*lane .. )
            crow += MM * (KK / 4);      // next b, same m
        }
    }

    // ---- argmax over 256 codewords: 128 packed k-pairs, 2 b's per thread ----
    float bva = -3.402823466e+38f, bvb = -3.402823466e+38f;
    int   bka = 0, bkb = 0;
#pragma unroll 4
    for (int j = 0; j < 128; j++) {
        const ulonglong2* cj = reinterpret_cast<const ulonglong2*>(&cpk[j * 8]);
        ulonglong2 c01 = cj[0], c23 = cj[1], c45 = cj[2], c67 = cj[3];

        // d-sequential fp32 accumulation (matches reference exactly)
        u64 acca = 0ull, accb = 0ull;
        acca = fma2(c01.x, xpa[0], acca);  accb = fma2(c01.x, xpb[0], accb);
        acca = fma2(c01.y, xpa[1], acca);  accb = fma2(c01.y, xpb[1], accb);
        acca = fma2(c23.x, xpa[2], acca);  accb = fma2(c23.x, xpb[2], accb);
        acca = fma2(c23.y, xpa[3], acca);  accb = fma2(c23.y, xpb[3], accb);
        acca = fma2(c45.x, xpa[4], acca);  accb = fma2(c45.x, xpb[4], accb);
        acca = fma2(c45.y, xpa[5], acca);  accb = fma2(c45.y, xpb[5], accb);
        acca = fma2(c67.x, xpa[6], acca);  accb = fma2(c67.x, xpb[6], accb);
        acca = fma2(c67.y, xpa[7], acca);  accb = fma2(c67.y, xpb[7], accb);

        float lo, hi;
        unpack2(acca, lo, hi);
        if (lo > bva) { bva = lo; bka = 2 * j; }       // strict >: lowest k ties
        if (hi > bva) { bva = hi; bka = 2 * j + 1; }
        unpack2(accb, lo, hi);
        if (lo > bvb) { bvb = lo; bkb = 2 * j; }
        if (hi > bvb) { bvb = hi; bkb = 2 * j + 1; }
    }

    // Order the zero stores before the 1.0 scatters (intra-warp fence).
    __syncwarp();

    // ---- scatter the single 1.0 per (b, m) row ----
    codes[((size_t)ba * MM + m) * KK + bka] = 1.0f;
    codes[((size_t)bb * MM + m) * KK + bkb] = 1.0f;

    // ---- x_hat: copy selected codewords (smem-hot) ----
    {
        float4* xh = reinterpret_cast<float4*>(xhat);
        const float4 va0 = craw[bka * 2], va1 = craw[bka * 2 + 1];
        __stcs(&xh[(size_t)ba * (FEAT / 4) + m * 2],     va0);
        __stcs(&xh[(size_t)ba * (FEAT / 4) + m * 2 + 1], va1);
        const float4 vb0 = craw[bkb * 2], vb1 = craw[bkb * 2 + 1];
        __stcs(&xh[(size_t)bb * (FEAT / 4) + m * 2],     vb0);
        __stcs(&xh[(size_t)bb * (FEAT / 4) + m * 2 + 1], vb1);
    }
}

extern "C" void kernel_launch(void* const* d_in, const int* in_sizes, int n_in,
                              void* d_out, int out_size)
{
    const float* x = (const float*)d_in[0];
    const float* C = (const float*)d_in[1];
    if (n_in >= 2 && in_sizes[0] == MM * KK * DD && in_sizes[1] == BB * FEAT) {
        x = (const float*)d_in[1];
        C = (const float*)d_in[0];
    }

    const long XHAT_N  = (long)BB * FEAT;        // 8,388,608
    const long CODES_N = (long)BB * MM * KK;     // 268,435,456

    float* xhat  = nullptr;
    float* codes = nullptr;
    if ((long)out_size >= XHAT_N + CODES_N) {
        xhat  = (float*)d_out;
        codes = (float*)d_out + XHAT_N;
    } else if ((long)out_size == CODES_N) {
        codes = (float*)d_out;
    } else {
        xhat = (float*)d_out;
    }

    dim3 grid(MM, BB / CHUNK_B);   // (64, 32)
    pq_forward_v3<<<grid, 256>>>(x, C, xhat, codes);
}

// round 4
// speedup vs baseline: 1.0518x; 1.0518x over previous
#include <cuda_runtime.h>
#include <cstdint>

// PQLayer forward on GB300 (sm_103a) — v4: two kernels split by store pattern.
//   A (m-major): argmax + coalesced zero-stream for codes + 1-byte idx scratch.
//   B (b-major): scatter 1.0s + contiguous x_hat rows (codeword gather).
//
// codes = stop_gradient(hard - soft) + soft == hard (one-hot) numerically.

#define BB 16384
#define MM 64
#define KK 256
#define DD 8
#define FEAT (MM * DD)          // 512
#define CHUNK_B 256             // b per block in kernel A (8 warps x 32)

using u64 = unsigned long long;

__device__ uint8_t g_idx[(size_t)MM * BB];   // scratch: idx[m][b], 1 MB

__device__ __forceinline__ u64 pack2(float lo, float hi) {
    u64 r;
    uint32_t a = __float_as_uint(lo), b = __float_as_uint(hi);
    asm("mov.b64 %0, {%1, %2};" : "=l"(r) : "r"(a), "r"(b));
    return r;
}

__device__ __forceinline__ void unpack2(u64 v, float& lo, float& hi) {
    uint32_t a, b;
    asm("mov.b64 {%0, %1}, %2;" : "=r"(a), "=r"(b) : "l"(v));
    lo = __uint_as_float(a);
    hi = __uint_as_float(b);
}

// Packed dual fp32 FMA (Blackwell FFMA2): IEEE fp32 per lane.
__device__ __forceinline__ u64 fma2(u64 a, u64 b, u64 c) {
    u64 r;
    asm("fma.rn.f32x2 %0, %1, %2, %3;" : "=l"(r) : "l"(a), "l"(b), "l"(c));
    return r;
}

// ---------------------------------------------------------------------------
// Kernel A: per-subspace argmax + zero-stream. Only coalesced stores.
// ---------------------------------------------------------------------------
__global__ void __launch_bounds__(256)
pq_argmax_zeros(const float* __restrict__ x, const float* __restrict__ C,
                float* __restrict__ codes)
{
    const int m    = blockIdx.x;
    const int tid  = threadIdx.x;
    const int lane = tid & 31;
    const int w    = tid >> 5;

    // cpk[j*8 + d] = { C[m][2j][d], C[m][2j+1][d] }  (k-pair packed, 8 KB)
    __shared__ __align__(16) u64 cpk[128 * 8];

    {
        const float4* C4 = reinterpret_cast<const float4*>(C) + (size_t)m * (KK * 2);
#pragma unroll
        for (int q = tid; q < KK * 2; q += 256) {
            float4 f = C4[q];
            const int k = q >> 1, h = (q & 1) * 4;
            const int j = k >> 1, half = k & 1;
            float vals[4] = {f.x, f.y, f.z, f.w};
#pragma unroll
            for (int dd = 0; dd < 4; dd++)
                reinterpret_cast<uint32_t*>(&cpk[j * 8 + h + dd])[half] =
                    __float_as_uint(vals[dd]);
        }
    }
    __syncthreads();

    const int b0w = blockIdx.y * CHUNK_B + w * 32;   // warp's first b
    const int b   = b0w + lane;

    // ---- load x[b, m*8 .. m*8+8], duplicate-pack for f32x2 ----
    const float4* x4 = reinterpret_cast<const float4*>(x) + (size_t)b * (FEAT / 4) + m * 2;
    const float4 xa = x4[0];
    const float4 xb = x4[1];
    u64 xp[8];
    xp[0] = pack2(xa.x, xa.x); xp[1] = pack2(xa.y, xa.y);
    xp[2] = pack2(xa.z, xa.z); xp[3] = pack2(xa.w, xa.w);
    xp[4] = pack2(xb.x, xb.x); xp[5] = pack2(xb.y, xb.y);
    xp[6] = pack2(xb.z, xb.z); xp[7] = pack2(xb.w, xb.w);

    // ---- stream zeros for this warp's 32 code rows (coalesced STG.128) ----
    {
        const float4 z = make_float4(0.f, 0.f, 0.f, 0.f);
        float4* crow = reinterpret_cast<float4*>(codes) +
                       ((size_t)b0w * MM + m) * (KK / 4) + lane;
#pragma unroll 8
        for (int r = 0; r < 32; r++) {
            __stcs(crow, z);            // k[4*lane .. 4*lane+4)
            __stcs(crow + 32, z);       // k[128+4*lane .. )
            crow += MM * (KK / 4);      // next b, same m
        }
    }

    // ---- argmax over 256 codewords: 128 packed k-pairs ----
    float bv = -3.402823466e+38f;
    int   bk = 0;
#pragma unroll 8
    for (int j = 0; j < 128; j++) {
        const ulonglong2* cj = reinterpret_cast<const ulonglong2*>(&cpk[j * 8]);
        ulonglong2 c01 = cj[0], c23 = cj[1], c45 = cj[2], c67 = cj[3];
        u64 acc = 0ull;                 // {+0, +0}; d-sequential fp32 accumulation
        acc = fma2(c01.x, xp[0], acc);
        acc = fma2(c01.y, xp[1], acc);
        acc = fma2(c23.x, xp[2], acc);
        acc = fma2(c23.y, xp[3], acc);
        acc = fma2(c45.x, xp[4], acc);
        acc = fma2(c45.y, xp[5], acc);
        acc = fma2(c67.x, xp[6], acc);
        acc = fma2(c67.y, xp[7], acc);
        float lo, hi;
        unpack2(acc, lo, hi);
        if (lo > bv) { bv = lo; bk = 2 * j; }       // strict >: lowest k wins ties
        if (hi > bv) { bv = hi; bk = 2 * j + 1; }
    }

    // ---- write idx byte (coalesced: 32 contiguous bytes per warp) ----
    g_idx[(size_t)m * BB + b] = (uint8_t)bk;
}

// ---------------------------------------------------------------------------
// Kernel B: b-major. Scatter 1.0s, gather codewords, contiguous x_hat rows.
// ---------------------------------------------------------------------------
__global__ void __launch_bounds__(256)
pq_scatter_xhat(const float* __restrict__ C,
                float* __restrict__ xhat, float* __restrict__ codes)
{
    const int lane = threadIdx.x & 31;
    const int w    = threadIdx.x >> 5;
    const int b    = blockIdx.x * 8 + w;       // warp owns one b

    const int m0 = lane;
    const int m1 = lane + 32;

    // idx reads: L2-hot (just written by kernel A)
    const int k0 = g_idx[(size_t)m0 * BB + b];
    const int k1 = g_idx[(size_t)m1 * BB + b];

    // ---- scatter the ones (rows already zeroed by kernel A) ----
    codes[((size_t)b * MM + m0) * KK + k0] = 1.0f;
    codes[((size_t)b * MM + m1) * KK + k1] = 1.0f;

    // ---- gather selected codewords (C is 2 MB -> L2-resident) ----
    const float4* C4 = reinterpret_cast<const float4*>(C);
    const float4 v00 = __ldg(&C4[((size_t)m0 * KK + k0) * 2]);
    const float4 v01 = __ldg(&C4[((size_t)m0 * KK + k0) * 2 + 1]);
    const float4 v10 = __ldg(&C4[((size_t)m1 * KK + k1) * 2]);
    const float4 v11 = __ldg(&C4[((size_t)m1 * KK + k1) * 2 + 1]);

    // ---- x_hat row b: contiguous across the warp (1 KB per instr) ----
    float4* xh = reinterpret_cast<float4*>(xhat) + (size_t)b * (FEAT / 4);
    __stcs(&xh[m0 * 2],     v00);
    __stcs(&xh[m0 * 2 + 1], v01);
    __stcs(&xh[m1 * 2],     v10);
    __stcs(&xh[m1 * 2 + 1], v11);
}

extern "C" void kernel_launch(void* const* d_in, const int* in_sizes, int n_in,
                              void* d_out, int out_size)
{
    const float* x = (const float*)d_in[0];
    const float* C = (const float*)d_in[1];
    if (n_in >= 2 && in_sizes[0] == MM * KK * DD && in_sizes[1] == BB * FEAT) {
        x = (const float*)d_in[1];
        C = (const float*)d_in[0];
    }

    const long XHAT_N  = (long)BB * FEAT;        // 8,388,608
    const long CODES_N = (long)BB * MM * KK;     // 268,435,456

    float* xhat  = nullptr;
    float* codes = nullptr;
    if ((long)out_size >= XHAT_N + CODES_N) {
        xhat  = (float*)d_out;
        codes = (float*)d_out + XHAT_N;
    } else if ((long)out_size == CODES_N) {
        codes = (float*)d_out;
    } else {
        xhat = (float*)d_out;
    }

    dim3 gridA(MM, BB / CHUNK_B);                // (64, 64)
    pq_argmax_zeros<<<gridA, 256>>>(x, C, codes);
    pq_scatter_xhat<<<BB / 8, 256>>>(C, xhat, codes);
}

// round 5
// speedup vs baseline: 1.2267x; 1.1662x over previous
#include <cuda_runtime.h>
#include <cstdint>

// PQLayer forward on GB300 (sm_103a) — v5: one-hot fused into the coalesced
// store stream (kills the DRAM read-modify-write scatter that was kernel B's
// 46 us in v4). B now only does idx->codeword gather + contiguous x_hat rows.
//
// codes = stop_gradient(hard - soft) + soft == hard (one-hot) numerically.

#define BB 16384
#define MM 64
#define KK 256
#define DD 8
#define FEAT (MM * DD)          // 512
#define CHUNK_B 256             // b per block in kernel A (8 warps x 32)

using u64 = unsigned long long;

__device__ uint8_t g_idx[(size_t)MM * BB];   // scratch: idx[m][b], 1 MB

__device__ __forceinline__ u64 pack2(float lo, float hi) {
    u64 r;
    uint32_t a = __float_as_uint(lo), b = __float_as_uint(hi);
    asm("mov.b64 %0, {%1, %2};" : "=l"(r) : "r"(a), "r"(b));
    return r;
}

__device__ __forceinline__ void unpack2(u64 v, float& lo, float& hi) {
    uint32_t a, b;
    asm("mov.b64 {%0, %1}, %2;" : "=r"(a), "=r"(b) : "l"(v));
    lo = __uint_as_float(a);
    hi = __uint_as_float(b);
}

// Packed dual fp32 FMA (Blackwell FFMA2): IEEE fp32 per lane.
__device__ __forceinline__ u64 fma2(u64 a, u64 b, u64 c) {
    u64 r;
    asm("fma.rn.f32x2 %0, %1, %2, %3;" : "=l"(r) : "l"(a), "l"(b), "l"(c));
    return r;
}

// ---------------------------------------------------------------------------
// Kernel A: per-subspace argmax, then fused one-hot row stream (coalesced,
// single-touch STG.128) + 1-byte idx for kernel B.
// ---------------------------------------------------------------------------
__global__ void __launch_bounds__(256)
pq_argmax_onehot(const float* __restrict__ x, const float* __restrict__ C,
                 float* __restrict__ codes)
{
    const int m    = blockIdx.x;
    const int tid  = threadIdx.x;
    const int lane = tid & 31;
    const int w    = tid >> 5;

    // cpk[j*8 + d] = { C[m][2j][d], C[m][2j+1][d] }  (k-pair packed, 8 KB)
    __shared__ __align__(16) u64 cpk[128 * 8];

    {
        const float4* C4 = reinterpret_cast<const float4*>(C) + (size_t)m * (KK * 2);
#pragma unroll
        for (int q = tid; q < KK * 2; q += 256) {
            float4 f = C4[q];
            const int k = q >> 1, h = (q & 1) * 4;
            const int j = k >> 1, half = k & 1;
            float vals[4] = {f.x, f.y, f.z, f.w};
#pragma unroll
            for (int dd = 0; dd < 4; dd++)
                reinterpret_cast<uint32_t*>(&cpk[j * 8 + h + dd])[half] =
                    __float_as_uint(vals[dd]);
        }
    }
    __syncthreads();

    const int b0w = blockIdx.y * CHUNK_B + w * 32;   // warp's first b
    const int b   = b0w + lane;

    // ---- load x[b, m*8 .. m*8+8], duplicate-pack for f32x2 ----
    const float4* x4 = reinterpret_cast<const float4*>(x) + (size_t)b * (FEAT / 4) + m * 2;
    const float4 xa = x4[0];
    const float4 xb = x4[1];
    u64 xp[8];
    xp[0] = pack2(xa.x, xa.x); xp[1] = pack2(xa.y, xa.y);
    xp[2] = pack2(xa.z, xa.z); xp[3] = pack2(xa.w, xa.w);
    xp[4] = pack2(xb.x, xb.x); xp[5] = pack2(xb.y, xb.y);
    xp[6] = pack2(xb.z, xb.z); xp[7] = pack2(xb.w, xb.w);

    // ---- argmax over 256 codewords: 128 packed k-pairs ----
    float bv = -3.402823466e+38f;
    int   bk = 0;
#pragma unroll 8
    for (int j = 0; j < 128; j++) {
        const ulonglong2* cj = reinterpret_cast<const ulonglong2*>(&cpk[j * 8]);
        ulonglong2 c01 = cj[0], c23 = cj[1], c45 = cj[2], c67 = cj[3];
        u64 acc = 0ull;                 // {+0, +0}; d-sequential fp32 accumulation
        acc = fma2(c01.x, xp[0], acc);
        acc = fma2(c01.y, xp[1], acc);
        acc = fma2(c23.x, xp[2], acc);
        acc = fma2(c23.y, xp[3], acc);
        acc = fma2(c45.x, xp[4], acc);
        acc = fma2(c45.y, xp[5], acc);
        acc = fma2(c67.x, xp[6], acc);
        acc = fma2(c67.y, xp[7], acc);
        float lo, hi;
        unpack2(acc, lo, hi);
        if (lo > bv) { bv = lo; bk = 2 * j; }       // strict >: lowest k wins ties
        if (hi > bv) { bv = hi; bk = 2 * j + 1; }
    }

    // ---- write idx byte (coalesced: 32 contiguous bytes per warp) ----
    g_idx[(size_t)m * BB + b] = (uint8_t)bk;

    // ---- fused one-hot stream: 32 rows, each written ONCE, coalesced ----
    // Row r belongs to b0w+r; its winner lives in lane r -> broadcast via shfl.
    {
        float4* crow = reinterpret_cast<float4*>(codes) +
                       ((size_t)b0w * MM + m) * (KK / 4) + lane;
        const int k0 = 4 * lane;          // this lane's first float4 covers k0..k0+3
        const int k1 = 128 + 4 * lane;    // second float4 covers k1..k1+3
#pragma unroll 8
        for (int r = 0; r < 32; r++) {
            const int ok = __shfl_sync(0xffffffffu, bk, r);
            float4 v0, v1;
            v0.x = (k0 + 0 == ok) ? 1.f : 0.f;
            v0.y = (k0 + 1 == ok) ? 1.f : 0.f;
            v0.z = (k0 + 2 == ok) ? 1.f : 0.f;
            v0.w = (k0 + 3 == ok) ? 1.f : 0.f;
            v1.x = (k1 + 0 == ok) ? 1.f : 0.f;
            v1.y = (k1 + 1 == ok) ? 1.f : 0.f;
            v1.z = (k1 + 2 == ok) ? 1.f : 0.f;
            v1.w = (k1 + 3 == ok) ? 1.f : 0.f;
            __stcs(crow, v0);             // k[4*lane .. 4*lane+4)
            __stcs(crow + 32, v1);        // k[128+4*lane .. )
            crow += MM * (KK / 4);        // next b, same m
        }
    }
}

// ---------------------------------------------------------------------------
// Kernel B: b-major. Gather selected codewords, contiguous x_hat rows.
// ---------------------------------------------------------------------------
__global__ void __launch_bounds__(256)
pq_xhat(const float* __restrict__ C, float* __restrict__ xhat)
{
    const int lane = threadIdx.x & 31;
    const int w    = threadIdx.x >> 5;
    const int b    = blockIdx.x * 8 + w;       // warp owns one b

    const int m0 = lane;
    const int m1 = lane + 32;

    // idx reads: L2-hot (just written by kernel A)
    const int k0 = g_idx[(size_t)m0 * BB + b];
    const int k1 = g_idx[(size_t)m1 * BB + b];

    // ---- gather selected codewords (C is 2 MB -> L2-resident) ----
    const float4* C4 = reinterpret_cast<const float4*>(C);
    const float4 v00 = __ldg(&C4[((size_t)m0 * KK + k0) * 2]);
    const float4 v01 = __ldg(&C4[((size_t)m0 * KK + k0) * 2 + 1]);
    const float4 v10 = __ldg(&C4[((size_t)m1 * KK + k1) * 2]);
    const float4 v11 = __ldg(&C4[((size_t)m1 * KK + k1) * 2 + 1]);

    // ---- x_hat row b: contiguous across the warp (1 KB per instr) ----
    float4* xh = reinterpret_cast<float4*>(xhat) + (size_t)b * (FEAT / 4);
    __stcs(&xh[m0 * 2],     v00);
    __stcs(&xh[m0 * 2 + 1], v01);
    __stcs(&xh[m1 * 2],     v10);
    __stcs(&xh[m1 * 2 + 1], v11);
}

extern "C" void kernel_launch(void* const* d_in, const int* in_sizes, int n_in,
                              void* d_out, int out_size)
{
    const float* x = (const float*)d_in[0];
    const float* C = (const float*)d_in[1];
    if (n_in >= 2 && in_sizes[0] == MM * KK * DD && in_sizes[1] == BB * FEAT) {
        x = (const float*)d_in[1];
        C = (const float*)d_in[0];
    }

    const long XHAT_N  = (long)BB * FEAT;        // 8,388,608
    const long CODES_N = (long)BB * MM * KK;     // 268,435,456

    float* xhat  = nullptr;
    float* codes = nullptr;
    if ((long)out_size >= XHAT_N + CODES_N) {
        xhat  = (float*)d_out;
        codes = (float*)d_out + XHAT_N;
    } else if ((long)out_size == CODES_N) {
        codes = (float*)d_out;
    } else {
        xhat = (float*)d_out;
    }

    dim3 gridA(MM, BB / CHUNK_B);                // (64, 64)
    pq_argmax_onehot<<<gridA, 256>>>(x, C, codes);
    if (xhat) pq_xhat<<<BB / 8, 256>>>(C, xhat);
}